// round 4
// baseline (speedup 1.0000x reference)
#include <cuda_runtime.h>
#include <math.h>

// Problem constants
#define CB 8
#define CN 1024
#define CD 512
#define CO 512
#define CH 8
#define CHD 64
#define QKVLD 1536   // 3*O
#define MROWS (CB*CN) // 8192

// ---------------- scratch (static device allocations; no cudaMalloc) ----------
__device__ float g_fmask[CB*CN];                     // converted mask
__device__ float g_qkv[CB*CN*3*CO];                  // 48 MB  [b,n, 3*O] row-major
__device__ float g_S[(size_t)CB*CH*CN*CN];           // 256 MB scores/attn
__device__ float g_H[CB*CN*CO];                      // 16 MB  attention output (masked)
__device__ float g_T[CB*CN*CO];                      // 16 MB  FFN hidden

// ---------------------------------------------------------------------------
// Mask conversion (dtype auto-detect over first 8192 bytes; data treated as
// data only).  int32 / uint8 / float32 / bf16 encodings supported.
// ---------------------------------------------------------------------------
__global__ void mask_convert(const unsigned char* __restrict__ raw,
                             float* __restrict__ fmask)
{
    __shared__ int s_m1, s_m23, s_gt1;
    int t = threadIdx.x;
    if (t == 0) { s_m1 = 0; s_m23 = 0; s_gt1 = 0; }
    __syncthreads();
    int m1 = 0, m23 = 0, g = 0;
    for (int i = t; i < CB*CN; i += 256) {
        unsigned char v = raw[i];
        if (v) {
            int p = i & 3;
            if (p == 1) m1 = 1;
            if (p >= 2) m23 = 1;
            if (v > 1) g = 1;
        }
    }
    if (m1)  atomicOr(&s_m1, 1);
    if (m23) atomicOr(&s_m23, 1);
    if (g)   atomicOr(&s_gt1, 1);
    __syncthreads();
    int mis = s_m1 | s_m23;
    int mode;            // 0=int32 1=uint8 2=float32 3=bf16
    if (!mis)            mode = 0;
    else if (!s_gt1)     mode = 1;
    else if (s_m1)       mode = 3;
    else                 mode = 2;
    for (int i = t; i < CB*CN; i += 256) {
        float f;
        if (mode == 0)      f = (((const int*)raw)[i]            != 0)   ? 1.f : 0.f;
        else if (mode == 1) f = (raw[i]                          != 0)   ? 1.f : 0.f;
        else if (mode == 2) f = (((const float*)raw)[i]          != 0.f) ? 1.f : 0.f;
        else                f = (((const unsigned short*)raw)[i] != 0)   ? 1.f : 0.f;
        fmask[i] = f;
    }
}

// ---------------------------------------------------------------------------
// Generic NT SGEMM:  C[m,n] = epi( sum_k A[m,k]*W[n,k] + bias[n] )
// 128x128 block tile, BK=8, 256 threads, 8x8 per thread.
// EPI: 0 -> C = v ; 1 -> C = relu(v) ; 2 -> C = 0.5*v ; 3 -> C += 0.5*fmask[m]*v
// ---------------------------------------------------------------------------
template<int EPI>
__global__ __launch_bounds__(256) void sgemm_nt(
    const float* __restrict__ A, const float* __restrict__ W,
    const float* __restrict__ bias, const float* __restrict__ fmask,
    float* __restrict__ C, int K, int lda, int ldw, int ldc)
{
    __shared__ __align__(16) float As[8][128];
    __shared__ __align__(16) float Bs[8][128];
    const int tid = threadIdx.x;
    const int tx = tid & 15, ty = tid >> 4;
    const int row0 = blockIdx.y * 128, col0 = blockIdx.x * 128;
    const int lr = tid >> 1;          // 0..127
    const int lk = (tid & 1) * 4;     // 0 or 4
    const float* Ap = A + (size_t)(row0 + lr) * lda + lk;
    const float* Wp = W + (size_t)(col0 + lr) * ldw + lk;

    float acc[8][8];
    #pragma unroll
    for (int i = 0; i < 8; i++)
        #pragma unroll
        for (int j = 0; j < 8; j++) acc[i][j] = 0.f;

    for (int k0 = 0; k0 < K; k0 += 8) {
        float4 av = *reinterpret_cast<const float4*>(Ap + k0);
        float4 wv = *reinterpret_cast<const float4*>(Wp + k0);
        As[lk+0][lr] = av.x; As[lk+1][lr] = av.y; As[lk+2][lr] = av.z; As[lk+3][lr] = av.w;
        Bs[lk+0][lr] = wv.x; Bs[lk+1][lr] = wv.y; Bs[lk+2][lr] = wv.z; Bs[lk+3][lr] = wv.w;
        __syncthreads();
        #pragma unroll
        for (int k = 0; k < 8; k++) {
            float4 a0 = *reinterpret_cast<const float4*>(&As[k][ty*8]);
            float4 a1 = *reinterpret_cast<const float4*>(&As[k][ty*8+4]);
            float4 b0 = *reinterpret_cast<const float4*>(&Bs[k][tx*8]);
            float4 b1 = *reinterpret_cast<const float4*>(&Bs[k][tx*8+4]);
            float a[8] = {a0.x,a0.y,a0.z,a0.w,a1.x,a1.y,a1.z,a1.w};
            float b[8] = {b0.x,b0.y,b0.z,b0.w,b1.x,b1.y,b1.z,b1.w};
            #pragma unroll
            for (int i = 0; i < 8; i++)
                #pragma unroll
                for (int j = 0; j < 8; j++)
                    acc[i][j] = fmaf(a[i], b[j], acc[i][j]);
        }
        __syncthreads();
    }

    #pragma unroll
    for (int i = 0; i < 8; i++) {
        int m = row0 + ty*8 + i;
        float fm = (EPI == 3) ? 0.5f * fmask[m] : 0.f;
        #pragma unroll
        for (int j = 0; j < 8; j++) {
            int n = col0 + tx*8 + j;
            float v = acc[i][j] + bias[n];
            size_t idx = (size_t)m * ldc + n;
            if (EPI == 0)      C[idx] = v;
            else if (EPI == 1) C[idx] = fmaxf(v, 0.f);
            else if (EPI == 2) C[idx] = 0.5f * v;
            else               C[idx] += fm * v;
        }
    }
}

// ---------------------------------------------------------------------------
// Scores per (b,h): S = Q K^T / 8 + diag(self_loop_W[h]), padding mask -> -1e6.
// ---------------------------------------------------------------------------
__global__ __launch_bounds__(256) void scores_kernel(
    const float* __restrict__ qkv, const float* __restrict__ slw,
    const float* __restrict__ fmask, float* __restrict__ S)
{
    __shared__ __align__(16) float As[8][128];
    __shared__ __align__(16) float Bs[8][128];
    const int z = blockIdx.z, b = z >> 3, h = z & 7;
    const float* Qb = qkv + (size_t)b * CN * QKVLD + h * CHD;
    const float* Kb = Qb + CO;
    float* Sb = S + (size_t)z * CN * CN;

    const int tid = threadIdx.x;
    const int tx = tid & 15, ty = tid >> 4;
    const int row0 = blockIdx.y * 128, col0 = blockIdx.x * 128;
    const int lr = tid >> 1;
    const int lk = (tid & 1) * 4;
    const float* Ap = Qb + (size_t)(row0 + lr) * QKVLD + lk;
    const float* Wp = Kb + (size_t)(col0 + lr) * QKVLD + lk;

    float acc[8][8];
    #pragma unroll
    for (int i = 0; i < 8; i++)
        #pragma unroll
        for (int j = 0; j < 8; j++) acc[i][j] = 0.f;

    for (int k0 = 0; k0 < CHD; k0 += 8) {
        float4 av = *reinterpret_cast<const float4*>(Ap + k0);
        float4 wv = *reinterpret_cast<const float4*>(Wp + k0);
        As[lk+0][lr] = av.x; As[lk+1][lr] = av.y; As[lk+2][lr] = av.z; As[lk+3][lr] = av.w;
        Bs[lk+0][lr] = wv.x; Bs[lk+1][lr] = wv.y; Bs[lk+2][lr] = wv.z; Bs[lk+3][lr] = wv.w;
        __syncthreads();
        #pragma unroll
        for (int k = 0; k < 8; k++) {
            float4 a0 = *reinterpret_cast<const float4*>(&As[k][ty*8]);
            float4 a1 = *reinterpret_cast<const float4*>(&As[k][ty*8+4]);
            float4 b0 = *reinterpret_cast<const float4*>(&Bs[k][tx*8]);
            float4 b1 = *reinterpret_cast<const float4*>(&Bs[k][tx*8+4]);
            float a[8] = {a0.x,a0.y,a0.z,a0.w,a1.x,a1.y,a1.z,a1.w};
            float bb[8] = {b0.x,b0.y,b0.z,b0.w,b1.x,b1.y,b1.z,b1.w};
            #pragma unroll
            for (int i = 0; i < 8; i++)
                #pragma unroll
                for (int j = 0; j < 8; j++)
                    acc[i][j] = fmaf(a[i], bb[j], acc[i][j]);
        }
        __syncthreads();
    }

    const float wdiag = slw[h];
    #pragma unroll
    for (int i = 0; i < 8; i++) {
        int m = row0 + ty*8 + i;
        float fr = fmask[b*CN + m];
        #pragma unroll
        for (int j = 0; j < 8; j++) {
            int n = col0 + tx*8 + j;
            float fc = fmask[b*CN + n];
            float s = acc[i][j] * 0.125f + ((m == n) ? wdiag : 0.f);
            if (fr == 0.f || fc == 0.f) s = -1e6f;
            Sb[(size_t)m * CN + n] = s;
        }
    }
}

// ---------------------------------------------------------------------------
// Row softmax over N=1024. One block per row, 256 threads x float4.
// ---------------------------------------------------------------------------
__global__ __launch_bounds__(256) void softmax_kernel(float* __restrict__ S)
{
    __shared__ float red[8];
    size_t row = blockIdx.x;
    float* p = S + row * CN;
    int t = threadIdx.x;
    float4 v = reinterpret_cast<float4*>(p)[t];

    float mx = fmaxf(fmaxf(v.x, v.y), fmaxf(v.z, v.w));
    #pragma unroll
    for (int o = 16; o; o >>= 1) mx = fmaxf(mx, __shfl_xor_sync(0xffffffffu, mx, o));
    if ((t & 31) == 0) red[t >> 5] = mx;
    __syncthreads();
    if (t == 0) {
        float m2 = red[0];
        #pragma unroll
        for (int i = 1; i < 8; i++) m2 = fmaxf(m2, red[i]);
        red[0] = m2;
    }
    __syncthreads();
    mx = red[0];
    __syncthreads();

    v.x = __expf(v.x - mx); v.y = __expf(v.y - mx);
    v.z = __expf(v.z - mx); v.w = __expf(v.w - mx);
    float sm = v.x + v.y + v.z + v.w;
    #pragma unroll
    for (int o = 16; o; o >>= 1) sm += __shfl_xor_sync(0xffffffffu, sm, o);
    if ((t & 31) == 0) red[t >> 5] = sm;
    __syncthreads();
    if (t == 0) {
        float s2 = 0.f;
        #pragma unroll
        for (int i = 0; i < 8; i++) s2 += red[i];
        red[0] = s2;
    }
    __syncthreads();
    float inv = 1.f / red[0];
    v.x *= inv; v.y *= inv; v.z *= inv; v.w *= inv;
    reinterpret_cast<float4*>(p)[t] = v;
}

// ---------------------------------------------------------------------------
// attn @ V per (b,h): C[n,d] = sum_m S[n,m]*V[m,d];  64x64 tile, BK=16.
// Epilogue applies first fmask multiply, scatters to merged-head layout.
// ---------------------------------------------------------------------------
__global__ __launch_bounds__(256) void av_kernel(
    const float* __restrict__ qkv, const float* __restrict__ S,
    const float* __restrict__ fmask, float* __restrict__ H)
{
    __shared__ __align__(16) float As[16][64];
    __shared__ __align__(16) float Bs[16][64];
    const int z = blockIdx.z, b = z >> 3, h = z & 7;
    const float* Sb = S + (size_t)z * CN * CN;
    const float* Vb = qkv + (size_t)b * CN * QKVLD + 2*CO + h * CHD;
    const int tid = threadIdx.x;
    const int tx = tid & 15, ty = tid >> 4;
    const int row0 = blockIdx.y * 64;
    const int ar = tid >> 2, akg = (tid & 3) * 4;   // A tile: 64 rows x 16 k
    const int vr = tid >> 4, vc = (tid & 15) * 4;   // V tile: 16 rows x 64 d

    float acc[4][4];
    #pragma unroll
    for (int i = 0; i < 4; i++)
        #pragma unroll
        for (int j = 0; j < 4; j++) acc[i][j] = 0.f;

    for (int k0 = 0; k0 < CN; k0 += 16) {
        float4 av = *reinterpret_cast<const float4*>(Sb + (size_t)(row0 + ar) * CN + k0 + akg);
        float4 vv = *reinterpret_cast<const float4*>(Vb + (size_t)(k0 + vr) * QKVLD + vc);
        As[akg+0][ar] = av.x; As[akg+1][ar] = av.y; As[akg+2][ar] = av.z; As[akg+3][ar] = av.w;
        *reinterpret_cast<float4*>(&Bs[vr][vc]) = vv;
        __syncthreads();
        #pragma unroll
        for (int k = 0; k < 16; k++) {
            float4 a  = *reinterpret_cast<const float4*>(&As[k][ty*4]);
            float4 bq = *reinterpret_cast<const float4*>(&Bs[k][tx*4]);
            float aa[4] = {a.x, a.y, a.z, a.w};
            float bb[4] = {bq.x, bq.y, bq.z, bq.w};
            #pragma unroll
            for (int i = 0; i < 4; i++)
                #pragma unroll
                for (int j = 0; j < 4; j++)
                    acc[i][j] = fmaf(aa[i], bb[j], acc[i][j]);
        }
        __syncthreads();
    }

    #pragma unroll
    for (int i = 0; i < 4; i++) {
        int m = row0 + ty*4 + i;
        float fm = fmask[b*CN + m];
        float* orow = H + (size_t)(b*CN + m) * CO + h * CHD + tx*4;
        float4 o;
        o.x = acc[i][0]*fm; o.y = acc[i][1]*fm; o.z = acc[i][2]*fm; o.w = acc[i][3]*fm;
        *reinterpret_cast<float4*>(orow) = o;
    }
}

// ---------------------------------------------------------------------------
// Input binding by element count (unique except w1/w2/wr + b1/b2/br ties;
// w-order preserved under both dict and alphabetical orderings, b* are zeros).
// ---------------------------------------------------------------------------
extern "C" void kernel_launch(void* const* d_in, const int* in_sizes, int n_in,
                              void* d_out, int out_size)
{
    const float* x = 0;  const unsigned char* mask_raw = 0;
    const float* slw = 0; const float* qkv_w = 0; const float* qkv_b = 0;
    const float* wbig[3] = {0,0,0}; const float* bsm[3] = {0,0,0};
    int nw = 0, nb = 0;

    for (int i = 0; i < n_in; i++) {
        switch (in_sizes[i]) {
            case 4194304: x        = (const float*)d_in[i]; break;         // [8,1024,512]
            case 8388608: /* adj unused */                  break;         // [8,1024,1024]
            case 8192:    mask_raw = (const unsigned char*)d_in[i]; break; // [8,1024]
            case 8:       slw      = (const float*)d_in[i]; break;         // [1,8,1,1]
            case 786432:  qkv_w    = (const float*)d_in[i]; break;         // [1536,512]
            case 1536:    qkv_b    = (const float*)d_in[i]; break;         // [1536]
            case 262144:  if (nw < 3) wbig[nw++] = (const float*)d_in[i]; break;
            case 512:     if (nb < 3) bsm[nb++]  = (const float*)d_in[i]; break;
            default: break;
        }
    }
    const float *w1 = wbig[0], *w2 = wbig[1], *wr = wbig[2];
    const float *b1 = bsm[0],  *b2 = bsm[1],  *br = bsm[2];
    float* out = (float*)d_out;

    // Resolve ALL scratch symbols through the runtime (a __device__ symbol
    // named directly in host code is NOT a valid device pointer).
    void *pf, *pq, *ps, *ph, *pt;
    cudaGetSymbolAddress(&pf, g_fmask);
    cudaGetSymbolAddress(&pq, g_qkv);
    cudaGetSymbolAddress(&ps, g_S);
    cudaGetSymbolAddress(&ph, g_H);
    cudaGetSymbolAddress(&pt, g_T);
    float* fmp  = (float*)pf;
    float* qkvp = (float*)pq;
    float* Sp   = (float*)ps;
    float* Hp   = (float*)ph;
    float* Tp   = (float*)pt;

    // 0) mask dtype detect + convert
    mask_convert<<<1, 256>>>(mask_raw, fmp);

    // 1) QKV = x @ qkv_w^T + qkv_b          [8192 x 1536], K=512
    sgemm_nt<0><<<dim3(12, 64), 256>>>(x, qkv_w, qkv_b, fmp, qkvp, CD, CD, CD, QKVLD);

    // 2) scores (scale + diag self-loop + mask) per (b,h)
    scores_kernel<<<dim3(8, 8, CB*CH), 256>>>(qkvp, slw, fmp, Sp);

    // 3) row softmax
    softmax_kernel<<<CB*CH*CN, 256>>>(Sp);

    // 4) H = (attn @ V) * fmask, merged-head layout
    av_kernel<<<dim3(1, 16, CB*CH), 256>>>(qkvp, Sp, fmp, Hp);

    // 5) T = relu(H @ w1^T + b1)            [8192 x 512], K=512
    sgemm_nt<1><<<dim3(4, 64), 256>>>(Hp, w1, b1, fmp, Tp, CO, CO, CO, CO);

    // 6) out = 0.5*(x @ wr^T + br)
    sgemm_nt<2><<<dim3(4, 64), 256>>>(x, wr, br, fmp, out, CD, CD, CD, CO);

    // 7) out += 0.5*fmask*(T @ w2^T + b2)
    sgemm_nt<3><<<dim3(4, 64), 256>>>(Tp, w2, b2, fmp, out, CO, CO, CO, CO);
}

// round 5
// speedup vs baseline: 1.7768x; 1.7768x over previous
#include <cuda_runtime.h>
#include <cuda_bf16.h>
#include <math.h>

// Problem constants
#define CB 8
#define CN 1024
#define CD 512
#define CO 512
#define CH 8
#define CHD 64
#define QKVLD 1536   // 3*O
#define MROWS (CB*CN) // 8192

// ---------------- scratch (static device allocations; no cudaMalloc) ----------
__device__ float g_fmask[MROWS];
__device__ __nv_bfloat16 g_xh[MROWS*CD],  g_xl[MROWS*CD];        // split x
__device__ __nv_bfloat16 g_qwh[QKVLD*CD], g_qwl[QKVLD*CD];       // split qkv_w
__device__ __nv_bfloat16 g_w1h[CO*CO], g_w1l[CO*CO];
__device__ __nv_bfloat16 g_w2h[CO*CO], g_w2l[CO*CO];
__device__ __nv_bfloat16 g_wrh[CO*CD], g_wrl[CO*CD];
__device__ __nv_bfloat16 g_qh[(size_t)MROWS*QKVLD], g_ql[(size_t)MROWS*QKVLD]; // split qkv out
__device__ float g_S[(size_t)CB*CH*CN*CN];                        // 256 MB scores
__device__ __nv_bfloat16 g_Ph[(size_t)CB*CH*CN*CN], g_Pl[(size_t)CB*CH*CN*CN]; // split attn probs
__device__ __nv_bfloat16 g_Hh[MROWS*CO], g_Hl[MROWS*CO];          // split attn output (masked)
__device__ __nv_bfloat16 g_Th[MROWS*CO], g_Tl[MROWS*CO];          // split FFN hidden

// ---------------------------------------------------------------------------
// helpers
// ---------------------------------------------------------------------------
__device__ __forceinline__ void bsplit(float v, __nv_bfloat16& h, __nv_bfloat16& l){
    h = __float2bfloat16(v);
    l = __float2bfloat16(v - __bfloat162float(h));
}
__device__ __forceinline__ unsigned packbf(__nv_bfloat16 e, __nv_bfloat16 o){
    return ((unsigned)__bfloat16_as_ushort(o) << 16) | (unsigned)__bfloat16_as_ushort(e);
}
// mma.sync m16n8k16 bf16, fp32 accum
__device__ __forceinline__ void mma16816(float* c, const unsigned* a, const unsigned* b){
    asm volatile("mma.sync.aligned.m16n8k16.row.col.f32.bf16.bf16.f32 "
        "{%0,%1,%2,%3}, {%4,%5,%6,%7}, {%8,%9}, {%0,%1,%2,%3};"
        : "+f"(c[0]), "+f"(c[1]), "+f"(c[2]), "+f"(c[3])
        : "r"(a[0]), "r"(a[1]), "r"(a[2]), "r"(a[3]), "r"(b[0]), "r"(b[1]));
}

// ---------------------------------------------------------------------------
// Mask conversion (dtype auto-detect; data treated strictly as data)
// ---------------------------------------------------------------------------
__global__ void mask_convert(const unsigned char* __restrict__ raw,
                             float* __restrict__ fmask)
{
    __shared__ int s_m1, s_m23, s_gt1;
    int t = threadIdx.x;
    if (t == 0) { s_m1 = 0; s_m23 = 0; s_gt1 = 0; }
    __syncthreads();
    int m1 = 0, m23 = 0, g = 0;
    for (int i = t; i < MROWS; i += 256) {
        unsigned char v = raw[i];
        if (v) {
            int p = i & 3;
            if (p == 1) m1 = 1;
            if (p >= 2) m23 = 1;
            if (v > 1) g = 1;
        }
    }
    if (m1)  atomicOr(&s_m1, 1);
    if (m23) atomicOr(&s_m23, 1);
    if (g)   atomicOr(&s_gt1, 1);
    __syncthreads();
    int mis = s_m1 | s_m23;
    int mode;            // 0=int32 1=uint8 2=float32 3=bf16
    if (!mis)            mode = 0;
    else if (!s_gt1)     mode = 1;
    else if (s_m1)       mode = 3;
    else                 mode = 2;
    for (int i = t; i < MROWS; i += 256) {
        float f;
        if (mode == 0)      f = (((const int*)raw)[i]            != 0)   ? 1.f : 0.f;
        else if (mode == 1) f = (raw[i]                          != 0)   ? 1.f : 0.f;
        else if (mode == 2) f = (((const float*)raw)[i]          != 0.f) ? 1.f : 0.f;
        else                f = (((const unsigned short*)raw)[i] != 0)   ? 1.f : 0.f;
        fmask[i] = f;
    }
}

// ---------------------------------------------------------------------------
// one-time fp32 -> (bf16 hi, bf16 lo) splitter
// ---------------------------------------------------------------------------
__global__ void split_kernel(const float* __restrict__ s,
                             __nv_bfloat16* __restrict__ h,
                             __nv_bfloat16* __restrict__ l, int n)
{
    int i = blockIdx.x * 256 + threadIdx.x;
    if (i < n) {
        __nv_bfloat16 hh, ll;
        bsplit(s[i], hh, ll);
        h[i] = hh; l[i] = ll;
    }
}

// ---------------------------------------------------------------------------
// Tensor-core NT GEMM (bf16x3 split):  C[m,n] = epi( sum_k A[m,k]*W[n,k] + bias[n] )
// Block tile 128x128, BK=16, 256 threads (8 warps = 2m x 4n), m16n8k16 mma.
// Operands are pre-split bf16 hi/lo arrays (k contiguous).
// EPI: 0 -> split-store bf16 hi/lo
//      1 -> relu, split-store bf16 hi/lo
//      2 -> Cf = 0.5*v (fp32)
//      3 -> Cf += 0.5*fmask[m]*v (fp32)
// ---------------------------------------------------------------------------
template<int EPI>
__global__ __launch_bounds__(256) void gemm_tc(
    const __nv_bfloat16* __restrict__ Ahg, const __nv_bfloat16* __restrict__ Alg,
    const __nv_bfloat16* __restrict__ Whg, const __nv_bfloat16* __restrict__ Wlg,
    const float* __restrict__ bias, const float* __restrict__ fmask,
    float* __restrict__ Cf, __nv_bfloat16* __restrict__ Ch, __nv_bfloat16* __restrict__ Cl,
    int K, int lda, int ldw, int ldc)
{
    __shared__ unsigned Ah[128*12], Al[128*12], Wh[128*12], Wl[128*12];
    const int tid = threadIdx.x;
    const int lane = tid & 31, wid = tid >> 5;
    const int wm = wid & 1, wn = wid >> 1;
    const int row0 = blockIdx.y * 128, col0 = blockIdx.x * 128;
    const int lr = tid >> 1, lh = tid & 1;       // loader: row, k-half
    const int qr = lane >> 2, qk = lane & 3;     // fragment lane decomposition

    float acc[4][4][4];
    #pragma unroll
    for (int mt = 0; mt < 4; mt++)
        #pragma unroll
        for (int nt = 0; nt < 4; nt++)
            #pragma unroll
            for (int i = 0; i < 4; i++) acc[mt][nt][i] = 0.f;

    for (int k0 = 0; k0 < K; k0 += 16) {
        size_t aoff = (size_t)(row0 + lr) * lda + k0 + lh * 8;
        size_t woff = (size_t)(col0 + lr) * ldw + k0 + lh * 8;
        uint4 va = *(const uint4*)(Ahg + aoff);
        uint4 vb = *(const uint4*)(Alg + aoff);
        uint4 vc = *(const uint4*)(Whg + woff);
        uint4 vd = *(const uint4*)(Wlg + woff);
        *(uint4*)&Ah[lr*12 + lh*4] = va;
        *(uint4*)&Al[lr*12 + lh*4] = vb;
        *(uint4*)&Wh[lr*12 + lh*4] = vc;
        *(uint4*)&Wl[lr*12 + lh*4] = vd;
        __syncthreads();

        unsigned afh[4][4], afl[4][4], bfh[4][2], bfl[4][2];
        #pragma unroll
        for (int mt = 0; mt < 4; mt++) {
            int base = (wm*64 + mt*16 + qr) * 12;
            afh[mt][0] = Ah[base + qk];      afh[mt][1] = Ah[base + 96 + qk];
            afh[mt][2] = Ah[base + qk + 4];  afh[mt][3] = Ah[base + 96 + qk + 4];
            afl[mt][0] = Al[base + qk];      afl[mt][1] = Al[base + 96 + qk];
            afl[mt][2] = Al[base + qk + 4];  afl[mt][3] = Al[base + 96 + qk + 4];
        }
        #pragma unroll
        for (int nt = 0; nt < 4; nt++) {
            int nb = (wn*32 + nt*8 + qr) * 12;
            bfh[nt][0] = Wh[nb + qk]; bfh[nt][1] = Wh[nb + qk + 4];
            bfl[nt][0] = Wl[nb + qk]; bfl[nt][1] = Wl[nb + qk + 4];
        }
        #pragma unroll
        for (int mt = 0; mt < 4; mt++)
            #pragma unroll
            for (int nt = 0; nt < 4; nt++) {
                mma16816(acc[mt][nt], afh[mt], bfh[nt]);
                mma16816(acc[mt][nt], afh[mt], bfl[nt]);
                mma16816(acc[mt][nt], afl[mt], bfh[nt]);
            }
        __syncthreads();
    }

    #pragma unroll
    for (int mt = 0; mt < 4; mt++)
        #pragma unroll
        for (int nt = 0; nt < 4; nt++) {
            const float* a = acc[mt][nt];
            int rbase = row0 + wm*64 + mt*16 + qr;
            int cbase = col0 + wn*32 + nt*8 + qk*2;
            float bv0 = bias[cbase], bv1 = bias[cbase + 1];
            #pragma unroll
            for (int hf = 0; hf < 2; hf++) {
                int r = rbase + hf*8;
                float v0 = a[hf*2+0] + bv0;
                float v1 = a[hf*2+1] + bv1;
                size_t idx = (size_t)r * ldc + cbase;
                if constexpr (EPI == 0 || EPI == 1) {
                    if constexpr (EPI == 1) { v0 = fmaxf(v0, 0.f); v1 = fmaxf(v1, 0.f); }
                    __nv_bfloat16 h0,l0,h1,l1;
                    bsplit(v0, h0, l0); bsplit(v1, h1, l1);
                    __nv_bfloat162 ph; ph.x = h0; ph.y = h1;
                    __nv_bfloat162 pl; pl.x = l0; pl.y = l1;
                    *(__nv_bfloat162*)(Ch + idx) = ph;
                    *(__nv_bfloat162*)(Cl + idx) = pl;
                } else if constexpr (EPI == 2) {
                    float2 o; o.x = 0.5f*v0; o.y = 0.5f*v1;
                    *(float2*)(Cf + idx) = o;
                } else {
                    float fm = 0.5f * fmask[r];
                    float2 cur = *(float2*)(Cf + idx);
                    cur.x += fm*v0; cur.y += fm*v1;
                    *(float2*)(Cf + idx) = cur;
                }
            }
        }
}

// ---------------------------------------------------------------------------
// Scores per (b,h): S = Q K^T / 8 + diag(self_loop_W[h]); mask -> -1e6.
// Same 128x128 bf16x3 body, K=64, operands from split qkv.
// ---------------------------------------------------------------------------
__global__ __launch_bounds__(256) void scores_tc(
    const __nv_bfloat16* __restrict__ qh, const __nv_bfloat16* __restrict__ ql,
    const float* __restrict__ slw, const float* __restrict__ fmask,
    float* __restrict__ S)
{
    __shared__ unsigned Ah[128*12], Al[128*12], Wh[128*12], Wl[128*12];
    const int z = blockIdx.z, b = z >> 3, h = z & 7;
    const __nv_bfloat16* Ahg = qh + (size_t)b*CN*QKVLD + h*CHD;
    const __nv_bfloat16* Alg = ql + (size_t)b*CN*QKVLD + h*CHD;
    const __nv_bfloat16* Whg = Ahg + CO;
    const __nv_bfloat16* Wlg = Alg + CO;
    float* Sb = S + (size_t)z*CN*CN;

    const int tid = threadIdx.x;
    const int lane = tid & 31, wid = tid >> 5;
    const int wm = wid & 1, wn = wid >> 1;
    const int row0 = blockIdx.y * 128, col0 = blockIdx.x * 128;
    const int lr = tid >> 1, lh = tid & 1;
    const int qr = lane >> 2, qk = lane & 3;

    float acc[4][4][4];
    #pragma unroll
    for (int mt = 0; mt < 4; mt++)
        #pragma unroll
        for (int nt = 0; nt < 4; nt++)
            #pragma unroll
            for (int i = 0; i < 4; i++) acc[mt][nt][i] = 0.f;

    for (int k0 = 0; k0 < CHD; k0 += 16) {
        size_t aoff = (size_t)(row0 + lr) * QKVLD + k0 + lh*8;
        size_t woff = (size_t)(col0 + lr) * QKVLD + k0 + lh*8;
        uint4 va = *(const uint4*)(Ahg + aoff);
        uint4 vb = *(const uint4*)(Alg + aoff);
        uint4 vc = *(const uint4*)(Whg + woff);
        uint4 vd = *(const uint4*)(Wlg + woff);
        *(uint4*)&Ah[lr*12 + lh*4] = va;
        *(uint4*)&Al[lr*12 + lh*4] = vb;
        *(uint4*)&Wh[lr*12 + lh*4] = vc;
        *(uint4*)&Wl[lr*12 + lh*4] = vd;
        __syncthreads();

        unsigned afh[4][4], afl[4][4], bfh[4][2], bfl[4][2];
        #pragma unroll
        for (int mt = 0; mt < 4; mt++) {
            int base = (wm*64 + mt*16 + qr) * 12;
            afh[mt][0] = Ah[base + qk];      afh[mt][1] = Ah[base + 96 + qk];
            afh[mt][2] = Ah[base + qk + 4];  afh[mt][3] = Ah[base + 96 + qk + 4];
            afl[mt][0] = Al[base + qk];      afl[mt][1] = Al[base + 96 + qk];
            afl[mt][2] = Al[base + qk + 4];  afl[mt][3] = Al[base + 96 + qk + 4];
        }
        #pragma unroll
        for (int nt = 0; nt < 4; nt++) {
            int nb = (wn*32 + nt*8 + qr) * 12;
            bfh[nt][0] = Wh[nb + qk]; bfh[nt][1] = Wh[nb + qk + 4];
            bfl[nt][0] = Wl[nb + qk]; bfl[nt][1] = Wl[nb + qk + 4];
        }
        #pragma unroll
        for (int mt = 0; mt < 4; mt++)
            #pragma unroll
            for (int nt = 0; nt < 4; nt++) {
                mma16816(acc[mt][nt], afh[mt], bfh[nt]);
                mma16816(acc[mt][nt], afh[mt], bfl[nt]);
                mma16816(acc[mt][nt], afl[mt], bfh[nt]);
            }
        __syncthreads();
    }

    const float wd = slw[h];
    #pragma unroll
    for (int mt = 0; mt < 4; mt++)
        #pragma unroll
        for (int nt = 0; nt < 4; nt++) {
            const float* a = acc[mt][nt];
            int rbase = row0 + wm*64 + mt*16 + qr;
            int cbase = col0 + wn*32 + nt*8 + qk*2;
            float fc0 = fmask[b*CN + cbase], fc1 = fmask[b*CN + cbase + 1];
            #pragma unroll
            for (int hf = 0; hf < 2; hf++) {
                int r = rbase + hf*8;
                float fr = fmask[b*CN + r];
                float v0 = a[hf*2+0]*0.125f + ((r == cbase)     ? wd : 0.f);
                float v1 = a[hf*2+1]*0.125f + ((r == cbase + 1) ? wd : 0.f);
                if (fr == 0.f || fc0 == 0.f) v0 = -1e6f;
                if (fr == 0.f || fc1 == 0.f) v1 = -1e6f;
                float2 o; o.x = v0; o.y = v1;
                *(float2*)(Sb + (size_t)r*CN + cbase) = o;
            }
        }
}

// ---------------------------------------------------------------------------
// Row softmax over N=1024; writes split bf16 probs (hi/lo).
// ---------------------------------------------------------------------------
__global__ __launch_bounds__(256) void softmax_split(
    const float* __restrict__ S,
    __nv_bfloat16* __restrict__ Ph, __nv_bfloat16* __restrict__ Pl)
{
    __shared__ float red[8];
    size_t row = blockIdx.x;
    const float* p = S + row * CN;
    int t = threadIdx.x;
    float4 v = reinterpret_cast<const float4*>(p)[t];

    float mx = fmaxf(fmaxf(v.x, v.y), fmaxf(v.z, v.w));
    #pragma unroll
    for (int o = 16; o; o >>= 1) mx = fmaxf(mx, __shfl_xor_sync(0xffffffffu, mx, o));
    if ((t & 31) == 0) red[t >> 5] = mx;
    __syncthreads();
    if (t == 0) {
        float m2 = red[0];
        #pragma unroll
        for (int i = 1; i < 8; i++) m2 = fmaxf(m2, red[i]);
        red[0] = m2;
    }
    __syncthreads();
    mx = red[0];
    __syncthreads();

    v.x = __expf(v.x - mx); v.y = __expf(v.y - mx);
    v.z = __expf(v.z - mx); v.w = __expf(v.w - mx);
    float sm = v.x + v.y + v.z + v.w;
    #pragma unroll
    for (int o = 16; o; o >>= 1) sm += __shfl_xor_sync(0xffffffffu, sm, o);
    if ((t & 31) == 0) red[t >> 5] = sm;
    __syncthreads();
    if (t == 0) {
        float s2 = 0.f;
        #pragma unroll
        for (int i = 0; i < 8; i++) s2 += red[i];
        red[0] = s2;
    }
    __syncthreads();
    float inv = 1.f / red[0];
    v.x *= inv; v.y *= inv; v.z *= inv; v.w *= inv;

    __nv_bfloat16 h0,l0,h1,l1,h2,l2,h3,l3;
    bsplit(v.x,h0,l0); bsplit(v.y,h1,l1); bsplit(v.z,h2,l2); bsplit(v.w,h3,l3);
    __nv_bfloat162* ph = (__nv_bfloat162*)(Ph + row*CN);
    __nv_bfloat162* pl = (__nv_bfloat162*)(Pl + row*CN);
    __nv_bfloat162 a; a.x=h0; a.y=h1;  ph[2*t]   = a;
    __nv_bfloat162 bq; bq.x=h2; bq.y=h3; ph[2*t+1] = bq;
    __nv_bfloat162 c; c.x=l0; c.y=l1;  pl[2*t]   = c;
    __nv_bfloat162 d; d.x=l2; d.y=l3;  pl[2*t+1] = d;
}

// ---------------------------------------------------------------------------
// attn @ V per (b,h), bf16x3: tile 128m x 64n, K=1024 (8 warps = 4m x 2n).
// Epilogue applies fmask and split-stores into merged-head layout.
// ---------------------------------------------------------------------------
__global__ __launch_bounds__(256) void av_tc(
    const __nv_bfloat16* __restrict__ Ph, const __nv_bfloat16* __restrict__ Pl,
    const __nv_bfloat16* __restrict__ qh, const __nv_bfloat16* __restrict__ ql,
    const float* __restrict__ fmask,
    __nv_bfloat16* __restrict__ Hh, __nv_bfloat16* __restrict__ Hl)
{
    __shared__ unsigned Ah[128*12], Al[128*12], Wh[64*12], Wl[64*12];
    const int z = blockIdx.z, b = z >> 3, h = z & 7;
    const __nv_bfloat16* Pzh = Ph + (size_t)z*CN*CN;
    const __nv_bfloat16* Pzl = Pl + (size_t)z*CN*CN;
    const __nv_bfloat16* Vh  = qh + (size_t)b*CN*QKVLD + 2*CO + h*CHD;
    const __nv_bfloat16* Vl  = ql + (size_t)b*CN*QKVLD + 2*CO + h*CHD;

    const int tid = threadIdx.x;
    const int lane = tid & 31, wid = tid >> 5;
    const int wm = wid & 3, wn = wid >> 2;
    const int row0 = blockIdx.y * 128;
    const int lr = tid >> 1, lh2 = tid & 1;
    const int vr = tid & 7, vn2 = (tid >> 3) * 2;   // V loader: k-pair idx, n pair
    const int qr = lane >> 2, qk = lane & 3;

    float acc[2][4][4];
    #pragma unroll
    for (int mt = 0; mt < 2; mt++)
        #pragma unroll
        for (int nt = 0; nt < 4; nt++)
            #pragma unroll
            for (int i = 0; i < 4; i++) acc[mt][nt][i] = 0.f;

    for (int k0 = 0; k0 < CN; k0 += 16) {
        size_t aoff = (size_t)(row0 + lr)*CN + k0 + lh2*8;
        uint4 va = *(const uint4*)(Pzh + aoff);
        uint4 vb = *(const uint4*)(Pzl + aoff);
        *(uint4*)&Ah[lr*12 + lh2*4] = va;
        *(uint4*)&Al[lr*12 + lh2*4] = vb;
        // V tile transpose-pack: rows k0+2vr, k0+2vr+1, cols vn2..vn2+1
        {
            const __nv_bfloat162 eh = *(const __nv_bfloat162*)(Vh + (size_t)(k0 + 2*vr)  *QKVLD + vn2);
            const __nv_bfloat162 oh = *(const __nv_bfloat162*)(Vh + (size_t)(k0 + 2*vr+1)*QKVLD + vn2);
            const __nv_bfloat162 el = *(const __nv_bfloat162*)(Vl + (size_t)(k0 + 2*vr)  *QKVLD + vn2);
            const __nv_bfloat162 ol = *(const __nv_bfloat162*)(Vl + (size_t)(k0 + 2*vr+1)*QKVLD + vn2);
            Wh[ vn2   *12 + vr] = packbf(eh.x, oh.x);
            Wh[(vn2+1)*12 + vr] = packbf(eh.y, oh.y);
            Wl[ vn2   *12 + vr] = packbf(el.x, ol.x);
            Wl[(vn2+1)*12 + vr] = packbf(el.y, ol.y);
        }
        __syncthreads();

        unsigned afh[2][4], afl[2][4], bfh[4][2], bfl[4][2];
        #pragma unroll
        for (int mt = 0; mt < 2; mt++) {
            int base = (wm*32 + mt*16 + qr) * 12;
            afh[mt][0] = Ah[base + qk];      afh[mt][1] = Ah[base + 96 + qk];
            afh[mt][2] = Ah[base + qk + 4];  afh[mt][3] = Ah[base + 96 + qk + 4];
            afl[mt][0] = Al[base + qk];      afl[mt][1] = Al[base + 96 + qk];
            afl[mt][2] = Al[base + qk + 4];  afl[mt][3] = Al[base + 96 + qk + 4];
        }
        #pragma unroll
        for (int nt = 0; nt < 4; nt++) {
            int nb = (wn*32 + nt*8 + qr) * 12;
            bfh[nt][0] = Wh[nb + qk]; bfh[nt][1] = Wh[nb + qk + 4];
            bfl[nt][0] = Wl[nb + qk]; bfl[nt][1] = Wl[nb + qk + 4];
        }
        #pragma unroll
        for (int mt = 0; mt < 2; mt++)
            #pragma unroll
            for (int nt = 0; nt < 4; nt++) {
                mma16816(acc[mt][nt], afh[mt], bfh[nt]);
                mma16816(acc[mt][nt], afh[mt], bfl[nt]);
                mma16816(acc[mt][nt], afl[mt], bfh[nt]);
            }
        __syncthreads();
    }

    #pragma unroll
    for (int mt = 0; mt < 2; mt++)
        #pragma unroll
        for (int nt = 0; nt < 4; nt++) {
            const float* a = acc[mt][nt];
            int rbase = row0 + wm*32 + mt*16 + qr;
            int n = wn*32 + nt*8 + qk*2;
            #pragma unroll
            for (int hf = 0; hf < 2; hf++) {
                int m = rbase + hf*8;
                float fm = fmask[b*CN + m];
                float v0 = a[hf*2+0] * fm;
                float v1 = a[hf*2+1] * fm;
                size_t idx = (size_t)(b*CN + m)*CO + h*CHD + n;
                __nv_bfloat16 h0,l0,h1,l1;
                bsplit(v0, h0, l0); bsplit(v1, h1, l1);
                __nv_bfloat162 ph; ph.x = h0; ph.y = h1;
                __nv_bfloat162 pl; pl.x = l0; pl.y = l1;
                *(__nv_bfloat162*)(Hh + idx) = ph;
                *(__nv_bfloat162*)(Hl + idx) = pl;
            }
        }
}

// ---------------------------------------------------------------------------
extern "C" void kernel_launch(void* const* d_in, const int* in_sizes, int n_in,
                              void* d_out, int out_size)
{
    const float* x = 0;  const unsigned char* mask_raw = 0;
    const float* slw = 0; const float* qkv_w = 0; const float* qkv_b = 0;
    const float* wbig[3] = {0,0,0}; const float* bsm[3] = {0,0,0};
    int nw = 0, nb = 0;

    for (int i = 0; i < n_in; i++) {
        switch (in_sizes[i]) {
            case 4194304: x        = (const float*)d_in[i]; break;
            case 8388608: /* adj unused */                  break;
            case 8192:    mask_raw = (const unsigned char*)d_in[i]; break;
            case 8:       slw      = (const float*)d_in[i]; break;
            case 786432:  qkv_w    = (const float*)d_in[i]; break;
            case 1536:    qkv_b    = (const float*)d_in[i]; break;
            case 262144:  if (nw < 3) wbig[nw++] = (const float*)d_in[i]; break;
            case 512:     if (nb < 3) bsm[nb++]  = (const float*)d_in[i]; break;
            default: break;
        }
    }
    const float *w1 = wbig[0], *w2 = wbig[1], *wr = wbig[2];
    const float *b1 = bsm[0],  *b2 = bsm[1],  *br = bsm[2];
    float* out = (float*)d_out;

    void *pf, *pxh, *pxl, *pqwh, *pqwl, *pw1h, *pw1l, *pw2h, *pw2l, *pwrh, *pwrl;
    void *pqh, *pql, *pS, *pPh, *pPl, *pHh, *pHl, *pTh, *pTl;
    cudaGetSymbolAddress(&pf,   g_fmask);
    cudaGetSymbolAddress(&pxh,  g_xh);   cudaGetSymbolAddress(&pxl,  g_xl);
    cudaGetSymbolAddress(&pqwh, g_qwh);  cudaGetSymbolAddress(&pqwl, g_qwl);
    cudaGetSymbolAddress(&pw1h, g_w1h);  cudaGetSymbolAddress(&pw1l, g_w1l);
    cudaGetSymbolAddress(&pw2h, g_w2h);  cudaGetSymbolAddress(&pw2l, g_w2l);
    cudaGetSymbolAddress(&pwrh, g_wrh);  cudaGetSymbolAddress(&pwrl, g_wrl);
    cudaGetSymbolAddress(&pqh,  g_qh);   cudaGetSymbolAddress(&pql,  g_ql);
    cudaGetSymbolAddress(&pS,   g_S);
    cudaGetSymbolAddress(&pPh,  g_Ph);   cudaGetSymbolAddress(&pPl,  g_Pl);
    cudaGetSymbolAddress(&pHh,  g_Hh);   cudaGetSymbolAddress(&pHl,  g_Hl);
    cudaGetSymbolAddress(&pTh,  g_Th);   cudaGetSymbolAddress(&pTl,  g_Tl);

    float* fmp = (float*)pf;
    __nv_bfloat16 *xh=(__nv_bfloat16*)pxh, *xl=(__nv_bfloat16*)pxl;
    __nv_bfloat16 *qwh=(__nv_bfloat16*)pqwh, *qwl=(__nv_bfloat16*)pqwl;
    __nv_bfloat16 *w1h=(__nv_bfloat16*)pw1h, *w1l=(__nv_bfloat16*)pw1l;
    __nv_bfloat16 *w2h=(__nv_bfloat16*)pw2h, *w2l=(__nv_bfloat16*)pw2l;
    __nv_bfloat16 *wrh=(__nv_bfloat16*)pwrh, *wrl=(__nv_bfloat16*)pwrl;
    __nv_bfloat16 *qhp=(__nv_bfloat16*)pqh, *qlp=(__nv_bfloat16*)pql;
    float* Sp = (float*)pS;
    __nv_bfloat16 *Php=(__nv_bfloat16*)pPh, *Plp=(__nv_bfloat16*)pPl;
    __nv_bfloat16 *Hhp=(__nv_bfloat16*)pHh, *Hlp=(__nv_bfloat16*)pHl;
    __nv_bfloat16 *Thp=(__nv_bfloat16*)pTh, *Tlp=(__nv_bfloat16*)pTl;

    // 0) mask convert + one-time splits
    mask_convert<<<1, 256>>>(mask_raw, fmp);
    split_kernel<<<(MROWS*CD+255)/256, 256>>>(x,     xh,  xl,  MROWS*CD);
    split_kernel<<<(QKVLD*CD+255)/256, 256>>>(qkv_w, qwh, qwl, QKVLD*CD);
    split_kernel<<<(CO*CO+255)/256,    256>>>(w1,    w1h, w1l, CO*CO);
    split_kernel<<<(CO*CO+255)/256,    256>>>(w2,    w2h, w2l, CO*CO);
    split_kernel<<<(CO*CD+255)/256,    256>>>(wr,    wrh, wrl, CO*CD);

    // 1) QKV = x @ qkv_w^T + qkv_b  -> split bf16
    gemm_tc<0><<<dim3(12, 64), 256>>>(xh, xl, qwh, qwl, qkv_b, fmp,
                                      (float*)0, qhp, qlp, CD, CD, CD, QKVLD);

    // 2) scores per (b,h)
    scores_tc<<<dim3(8, 8, CB*CH), 256>>>(qhp, qlp, slw, fmp, Sp);

    // 3) softmax -> split probs
    softmax_split<<<CB*CH*CN, 256>>>(Sp, Php, Plp);

    // 4) H = (attn @ V) * fmask -> split bf16 (merged-head layout)
    av_tc<<<dim3(1, 8, CB*CH), 256>>>(Php, Plp, qhp, qlp, fmp, Hhp, Hlp);

    // 5) T = relu(H @ w1^T + b1) -> split bf16
    gemm_tc<1><<<dim3(4, 64), 256>>>(Hhp, Hlp, w1h, w1l, b1, fmp,
                                     (float*)0, Thp, Tlp, CO, CO, CO, CO);

    // 6) out = 0.5*(x @ wr^T + br)
    gemm_tc<2><<<dim3(4, 64), 256>>>(xh, xl, wrh, wrl, br, fmp,
                                     out, (__nv_bfloat16*)0, (__nv_bfloat16*)0, CD, CD, CD, CO);

    // 7) out += 0.5*fmask*(T @ w2^T + b2)
    gemm_tc<3><<<dim3(4, 64), 256>>>(Thp, Tlp, w2h, w2l, b2, fmp,
                                     out, (__nv_bfloat16*)0, (__nv_bfloat16*)0, CO, CO, CO, CO);
}

// round 6
// speedup vs baseline: 2.1675x; 1.2199x over previous
#include <cuda_runtime.h>
#include <cuda_bf16.h>
#include <math.h>

// Problem constants
#define CB 8
#define CN 1024
#define CD 512
#define CO 512
#define CH 8
#define CHD 64
#define QKVLD 1536   // 3*O
#define MROWS (CB*CN) // 8192

// ---------------- scratch (static device allocations; no cudaMalloc) ----------
__device__ float g_fmask[MROWS];
__device__ __nv_bfloat16 g_xh[MROWS*CD],  g_xl[MROWS*CD];
__device__ __nv_bfloat16 g_qwh[QKVLD*CD], g_qwl[QKVLD*CD];
__device__ __nv_bfloat16 g_w1h[CO*CO], g_w1l[CO*CO];
__device__ __nv_bfloat16 g_w2h[CO*CO], g_w2l[CO*CO];
__device__ __nv_bfloat16 g_wrh[CO*CD], g_wrl[CO*CD];
__device__ __nv_bfloat16 g_qh[(size_t)MROWS*QKVLD], g_ql[(size_t)MROWS*QKVLD];
__device__ __nv_bfloat16 g_Hh[MROWS*CO], g_Hl[MROWS*CO];
__device__ __nv_bfloat16 g_Th[MROWS*CO], g_Tl[MROWS*CO];

// ---------------------------------------------------------------------------
__device__ __forceinline__ void bsplit(float v, __nv_bfloat16& h, __nv_bfloat16& l){
    h = __float2bfloat16(v);
    l = __float2bfloat16(v - __bfloat162float(h));
}
__device__ __forceinline__ unsigned packbf(__nv_bfloat16 e, __nv_bfloat16 o){
    return ((unsigned)__bfloat16_as_ushort(o) << 16) | (unsigned)__bfloat16_as_ushort(e);
}
__device__ __forceinline__ unsigned packhi(float a, float b){
    __nv_bfloat162 t = __floats2bfloat162_rn(a, b);  // x=a (low), y=b (high)
    return *(unsigned*)&t;
}
__device__ __forceinline__ void mma16816(float* c, const unsigned* a, const unsigned* b){
    asm volatile("mma.sync.aligned.m16n8k16.row.col.f32.bf16.bf16.f32 "
        "{%0,%1,%2,%3}, {%4,%5,%6,%7}, {%8,%9}, {%0,%1,%2,%3};"
        : "+f"(c[0]), "+f"(c[1]), "+f"(c[2]), "+f"(c[3])
        : "r"(a[0]), "r"(a[1]), "r"(a[2]), "r"(a[3]), "r"(b[0]), "r"(b[1]));
}

// ---------------------------------------------------------------------------
// Mask conversion (dtype auto-detect; bench data treated strictly as data)
// ---------------------------------------------------------------------------
__global__ void mask_convert(const unsigned char* __restrict__ raw,
                             float* __restrict__ fmask)
{
    __shared__ int s_m1, s_m23, s_gt1;
    int t = threadIdx.x;
    if (t == 0) { s_m1 = 0; s_m23 = 0; s_gt1 = 0; }
    __syncthreads();
    int m1 = 0, m23 = 0, g = 0;
    for (int i = t; i < MROWS; i += 256) {
        unsigned char v = raw[i];
        if (v) {
            int p = i & 3;
            if (p == 1) m1 = 1;
            if (p >= 2) m23 = 1;
            if (v > 1) g = 1;
        }
    }
    if (m1)  atomicOr(&s_m1, 1);
    if (m23) atomicOr(&s_m23, 1);
    if (g)   atomicOr(&s_gt1, 1);
    __syncthreads();
    int mis = s_m1 | s_m23;
    int mode;
    if (!mis)            mode = 0;
    else if (!s_gt1)     mode = 1;
    else if (s_m1)       mode = 3;
    else                 mode = 2;
    for (int i = t; i < MROWS; i += 256) {
        float f;
        if (mode == 0)      f = (((const int*)raw)[i]            != 0)   ? 1.f : 0.f;
        else if (mode == 1) f = (raw[i]                          != 0)   ? 1.f : 0.f;
        else if (mode == 2) f = (((const float*)raw)[i]          != 0.f) ? 1.f : 0.f;
        else                f = (((const unsigned short*)raw)[i] != 0)   ? 1.f : 0.f;
        fmask[i] = f;
    }
}

__global__ void split_kernel(const float* __restrict__ s,
                             __nv_bfloat16* __restrict__ h,
                             __nv_bfloat16* __restrict__ l, int n)
{
    int i = blockIdx.x * 256 + threadIdx.x;
    if (i < n) {
        __nv_bfloat16 hh, ll;
        bsplit(s[i], hh, ll);
        h[i] = hh; l[i] = ll;
    }
}

// ---------------------------------------------------------------------------
// Tensor-core NT GEMM (bf16x3): C[m,n] = epi( sum_k A[m,k]*W[n,k] + bias[n] )
// 128x128, BK=16, 256 thr (8 warps = 2m x 4n).
// EPI: 0 split-store; 1 relu+split-store; 2 Cf=0.5v; 3 Cf+=0.5*fmask[m]*v
// ---------------------------------------------------------------------------
template<int EPI>
__global__ __launch_bounds__(256) void gemm_tc(
    const __nv_bfloat16* __restrict__ Ahg, const __nv_bfloat16* __restrict__ Alg,
    const __nv_bfloat16* __restrict__ Whg, const __nv_bfloat16* __restrict__ Wlg,
    const float* __restrict__ bias, const float* __restrict__ fmask,
    float* __restrict__ Cf, __nv_bfloat16* __restrict__ Ch, __nv_bfloat16* __restrict__ Cl,
    int K, int lda, int ldw, int ldc)
{
    __shared__ unsigned Ah[128*12], Al[128*12], Wh[128*12], Wl[128*12];
    const int tid = threadIdx.x;
    const int lane = tid & 31, wid = tid >> 5;
    const int wm = wid & 1, wn = wid >> 1;
    const int row0 = blockIdx.y * 128, col0 = blockIdx.x * 128;
    const int lr = tid >> 1, lh = tid & 1;
    const int qr = lane >> 2, qk = lane & 3;

    float acc[4][4][4];
    #pragma unroll
    for (int mt = 0; mt < 4; mt++)
        #pragma unroll
        for (int nt = 0; nt < 4; nt++)
            #pragma unroll
            for (int i = 0; i < 4; i++) acc[mt][nt][i] = 0.f;

    for (int k0 = 0; k0 < K; k0 += 16) {
        size_t aoff = (size_t)(row0 + lr) * lda + k0 + lh * 8;
        size_t woff = (size_t)(col0 + lr) * ldw + k0 + lh * 8;
        uint4 va = *(const uint4*)(Ahg + aoff);
        uint4 vb = *(const uint4*)(Alg + aoff);
        uint4 vc = *(const uint4*)(Whg + woff);
        uint4 vd = *(const uint4*)(Wlg + woff);
        *(uint4*)&Ah[lr*12 + lh*4] = va;
        *(uint4*)&Al[lr*12 + lh*4] = vb;
        *(uint4*)&Wh[lr*12 + lh*4] = vc;
        *(uint4*)&Wl[lr*12 + lh*4] = vd;
        __syncthreads();

        unsigned afh[4][4], afl[4][4], bfh[4][2], bfl[4][2];
        #pragma unroll
        for (int mt = 0; mt < 4; mt++) {
            int base = (wm*64 + mt*16 + qr) * 12;
            afh[mt][0] = Ah[base + qk];      afh[mt][1] = Ah[base + 96 + qk];
            afh[mt][2] = Ah[base + qk + 4];  afh[mt][3] = Ah[base + 96 + qk + 4];
            afl[mt][0] = Al[base + qk];      afl[mt][1] = Al[base + 96 + qk];
            afl[mt][2] = Al[base + qk + 4];  afl[mt][3] = Al[base + 96 + qk + 4];
        }
        #pragma unroll
        for (int nt = 0; nt < 4; nt++) {
            int nb = (wn*32 + nt*8 + qr) * 12;
            bfh[nt][0] = Wh[nb + qk]; bfh[nt][1] = Wh[nb + qk + 4];
            bfl[nt][0] = Wl[nb + qk]; bfl[nt][1] = Wl[nb + qk + 4];
        }
        #pragma unroll
        for (int mt = 0; mt < 4; mt++)
            #pragma unroll
            for (int nt = 0; nt < 4; nt++) {
                mma16816(acc[mt][nt], afh[mt], bfh[nt]);
                mma16816(acc[mt][nt], afh[mt], bfl[nt]);
                mma16816(acc[mt][nt], afl[mt], bfh[nt]);
            }
        __syncthreads();
    }

    #pragma unroll
    for (int mt = 0; mt < 4; mt++)
        #pragma unroll
        for (int nt = 0; nt < 4; nt++) {
            const float* a = acc[mt][nt];
            int rbase = row0 + wm*64 + mt*16 + qr;
            int cbase = col0 + wn*32 + nt*8 + qk*2;
            float bv0 = bias[cbase], bv1 = bias[cbase + 1];
            #pragma unroll
            for (int hf = 0; hf < 2; hf++) {
                int r = rbase + hf*8;
                float v0 = a[hf*2+0] + bv0;
                float v1 = a[hf*2+1] + bv1;
                size_t idx = (size_t)r * ldc + cbase;
                if constexpr (EPI == 0 || EPI == 1) {
                    if constexpr (EPI == 1) { v0 = fmaxf(v0, 0.f); v1 = fmaxf(v1, 0.f); }
                    __nv_bfloat16 h0,l0,h1,l1;
                    bsplit(v0, h0, l0); bsplit(v1, h1, l1);
                    __nv_bfloat162 ph; ph.x = h0; ph.y = h1;
                    __nv_bfloat162 pl; pl.x = l0; pl.y = l1;
                    *(__nv_bfloat162*)(Ch + idx) = ph;
                    *(__nv_bfloat162*)(Cl + idx) = pl;
                } else if constexpr (EPI == 2) {
                    float2 o; o.x = 0.5f*v0; o.y = 0.5f*v1;
                    *(float2*)(Cf + idx) = o;
                } else {
                    float fm = 0.5f * fmask[r];
                    float2 cur = *(float2*)(Cf + idx);
                    cur.x += fm*v0; cur.y += fm*v1;
                    *(float2*)(Cf + idx) = cur;
                }
            }
        }
}

// ---------------------------------------------------------------------------
// Flash-fused attention (bf16x3, online softmax, P register-resident).
// Grid: (CN/128, B*H). Block 256 thr = 8 warps, each warp 16 Q rows.
// SMEM (dynamic): K tile hi/lo [128 rows x 36 u32], V tile hi/lo [64 n x 68 u32],
// col-mask [128 f32]. Q staged through the K buffers before the mainloop.
// ---------------------------------------------------------------------------
#define KS_STRIDE 36
#define VS_STRIDE 68
#define KS_WORDS (128*KS_STRIDE)      // 4608
#define VS_WORDS (64*VS_STRIDE)       // 4352
#define FL_SMEM_BYTES ((2*KS_WORDS + 2*VS_WORDS + 128) * 4)  // 72192

__global__ void __launch_bounds__(256, 1) flash_tc(
    const __nv_bfloat16* __restrict__ qh, const __nv_bfloat16* __restrict__ ql,
    const float* __restrict__ slw, const float* __restrict__ fmask,
    __nv_bfloat16* __restrict__ Hh, __nv_bfloat16* __restrict__ Hl)
{
    extern __shared__ unsigned smem[];
    unsigned* Ksh = smem;
    unsigned* Ksl = smem + KS_WORDS;
    unsigned* Vsh = smem + 2*KS_WORDS;
    unsigned* Vsl = smem + 2*KS_WORDS + VS_WORDS;
    float*    cm  = (float*)(smem + 2*KS_WORDS + 2*VS_WORDS);

    const int z = blockIdx.y, b = z >> 3, h = z & 7;
    const int qt = blockIdx.x;
    const int tid = threadIdx.x;
    const int lane = tid & 31, wid = tid >> 5;
    const int qr = lane >> 2, qk = lane & 3;

    const size_t bhq = (size_t)b*CN*QKVLD + h*CHD;       // Q base
    const size_t bhk = bhq + CO;                          // K base
    const size_t bhv = bhq + 2*CO;                        // V base

    const int lrow = tid >> 1, lq = tid & 1;              // loader mapping (K/Q)
    const int vn2 = (tid >> 3) * 2, vr = tid & 7;         // V transpose-pack mapping

    // ---- stage Q tile through K buffers, pull fragments to registers ----
    {
        size_t qoff = bhq + (size_t)(qt*128 + lrow)*QKVLD + lq*32;
        #pragma unroll
        for (int i = 0; i < 4; i++) {
            *(uint4*)&Ksh[lrow*KS_STRIDE + lq*16 + i*4] = *(const uint4*)(qh + qoff + i*8);
            *(uint4*)&Ksl[lrow*KS_STRIDE + lq*16 + i*4] = *(const uint4*)(ql + qoff + i*8);
        }
    }
    __syncthreads();
    unsigned qfh[4][4], qfl[4][4];
    #pragma unroll
    for (int kw = 0; kw < 4; kw++) {
        int r0 = (wid*16 + qr) * KS_STRIDE + kw*8;
        int r8 = (wid*16 + qr + 8) * KS_STRIDE + kw*8;
        qfh[kw][0] = Ksh[r0 + qk];     qfh[kw][1] = Ksh[r8 + qk];
        qfh[kw][2] = Ksh[r0 + qk + 4]; qfh[kw][3] = Ksh[r8 + qk + 4];
        qfl[kw][0] = Ksl[r0 + qk];     qfl[kw][1] = Ksl[r8 + qk];
        qfl[kw][2] = Ksl[r0 + qk + 4]; qfl[kw][3] = Ksl[r8 + qk + 4];
    }
    __syncthreads();

    const float wd = slw[h];
    float o[8][4];
    #pragma unroll
    for (int i = 0; i < 8; i++)
        #pragma unroll
        for (int j = 0; j < 4; j++) o[i][j] = 0.f;
    float m0 = -1e30f, m1 = -1e30f, l0 = 0.f, l1 = 0.f;

    for (int kt = 0; kt < 8; kt++) {
        // ---- load K tile + col mask + V tile (transposed) ----
        {
            size_t koff = bhk + (size_t)(kt*128 + lrow)*QKVLD + lq*32;
            #pragma unroll
            for (int i = 0; i < 4; i++) {
                *(uint4*)&Ksh[lrow*KS_STRIDE + lq*16 + i*4] = *(const uint4*)(qh + koff + i*8);
                *(uint4*)&Ksl[lrow*KS_STRIDE + lq*16 + i*4] = *(const uint4*)(ql + koff + i*8);
            }
            if (tid < 128) cm[tid] = fmask[b*CN + kt*128 + tid];
            #pragma unroll
            for (int w8 = 0; w8 < 8; w8++) {
                size_t t0 = bhv + (size_t)(kt*128 + w8*16 + 2*vr)*QKVLD + vn2;
                __nv_bfloat162 eh = *(const __nv_bfloat162*)(qh + t0);
                __nv_bfloat162 oh = *(const __nv_bfloat162*)(qh + t0 + QKVLD);
                __nv_bfloat162 el = *(const __nv_bfloat162*)(ql + t0);
                __nv_bfloat162 ol = *(const __nv_bfloat162*)(ql + t0 + QKVLD);
                Vsh[ vn2   *VS_STRIDE + w8*8 + vr] = packbf(eh.x, oh.x);
                Vsh[(vn2+1)*VS_STRIDE + w8*8 + vr] = packbf(eh.y, oh.y);
                Vsl[ vn2   *VS_STRIDE + w8*8 + vr] = packbf(el.x, ol.x);
                Vsl[(vn2+1)*VS_STRIDE + w8*8 + vr] = packbf(el.y, ol.y);
            }
        }
        __syncthreads();

        // ---- S = Q K^T (bf16x3) ----
        float s[16][4];
        #pragma unroll
        for (int nt = 0; nt < 16; nt++)
            #pragma unroll
            for (int i = 0; i < 4; i++) s[nt][i] = 0.f;

        #pragma unroll
        for (int nt = 0; nt < 16; nt++) {
            int nb = (nt*8 + qr) * KS_STRIDE;
            #pragma unroll
            for (int kw = 0; kw < 4; kw++) {
                unsigned bh[2] = { Ksh[nb + kw*8 + qk], Ksh[nb + kw*8 + qk + 4] };
                unsigned bl[2] = { Ksl[nb + kw*8 + qk], Ksl[nb + kw*8 + qk + 4] };
                mma16816(s[nt], qfh[kw], bh);
                mma16816(s[nt], qfh[kw], bl);
                mma16816(s[nt], qfl[kw], bh);
            }
        }

        // ---- scale + diag + col-mask, online softmax ----
        const int lr0 = wid*16 + qr, lr1 = lr0 + 8;
        float tmax0 = -3e38f, tmax1 = -3e38f;
        #pragma unroll
        for (int nt = 0; nt < 16; nt++) {
            int c0 = nt*8 + qk*2;
            float2 cmv = *(const float2*)(cm + c0);
            float v0 = s[nt][0]*0.125f, v1 = s[nt][1]*0.125f;
            float v2 = s[nt][2]*0.125f, v3 = s[nt][3]*0.125f;
            if (qt == kt) {
                if (lr0 == c0)     v0 += wd;
                if (lr0 == c0 + 1) v1 += wd;
                if (lr1 == c0)     v2 += wd;
                if (lr1 == c0 + 1) v3 += wd;
            }
            if (cmv.x == 0.f) { v0 = -1e6f; v2 = -1e6f; }
            if (cmv.y == 0.f) { v1 = -1e6f; v3 = -1e6f; }
            s[nt][0] = v0; s[nt][1] = v1; s[nt][2] = v2; s[nt][3] = v3;
            tmax0 = fmaxf(tmax0, fmaxf(v0, v1));
            tmax1 = fmaxf(tmax1, fmaxf(v2, v3));
        }
        #pragma unroll
        for (int off = 1; off <= 2; off <<= 1) {
            tmax0 = fmaxf(tmax0, __shfl_xor_sync(0xffffffffu, tmax0, off));
            tmax1 = fmaxf(tmax1, __shfl_xor_sync(0xffffffffu, tmax1, off));
        }
        float mn0 = fmaxf(m0, tmax0), mn1 = fmaxf(m1, tmax1);
        float sc0 = __expf(m0 - mn0), sc1 = __expf(m1 - mn1);
        m0 = mn0; m1 = mn1;
        l0 *= sc0; l1 *= sc1;
        #pragma unroll
        for (int nt2 = 0; nt2 < 8; nt2++) {
            o[nt2][0] *= sc0; o[nt2][1] *= sc0;
            o[nt2][2] *= sc1; o[nt2][3] *= sc1;
        }
        float rs0 = 0.f, rs1 = 0.f;
        #pragma unroll
        for (int nt = 0; nt < 16; nt++) {
            float p0 = __expf(s[nt][0] - mn0);
            float p1 = __expf(s[nt][1] - mn0);
            float p2 = __expf(s[nt][2] - mn1);
            float p3 = __expf(s[nt][3] - mn1);
            rs0 += p0 + p1; rs1 += p2 + p3;
            s[nt][0] = p0; s[nt][1] = p1; s[nt][2] = p2; s[nt][3] = p3;
        }
        #pragma unroll
        for (int off = 1; off <= 2; off <<= 1) {
            rs0 += __shfl_xor_sync(0xffffffffu, rs0, off);
            rs1 += __shfl_xor_sync(0xffffffffu, rs1, off);
        }
        l0 += rs0; l1 += rs1;

        // ---- O += P V (bf16x3, P packed from registers) ----
        #pragma unroll
        for (int kk = 0; kk < 8; kk++) {
            const float* t0 = s[2*kk];
            const float* t1 = s[2*kk + 1];
            unsigned ah[4], al[4];
            {
                __nv_bfloat16 h00,l00,h01,l01,h02,l02,h03,l03;
                bsplit(t0[0],h00,l00); bsplit(t0[1],h01,l01);
                bsplit(t0[2],h02,l02); bsplit(t0[3],h03,l03);
                ah[0] = packbf(h00,h01); al[0] = packbf(l00,l01);
                ah[1] = packbf(h02,h03); al[1] = packbf(l02,l03);
                __nv_bfloat16 h10,l10,h11,l11,h12,l12,h13,l13;
                bsplit(t1[0],h10,l10); bsplit(t1[1],h11,l11);
                bsplit(t1[2],h12,l12); bsplit(t1[3],h13,l13);
                ah[2] = packbf(h10,h11); al[2] = packbf(l10,l11);
                ah[3] = packbf(h12,h13); al[3] = packbf(l12,l13);
            }
            #pragma unroll
            for (int nt2 = 0; nt2 < 8; nt2++) {
                int vb2 = (nt2*8 + qr) * VS_STRIDE + kk*8;
                unsigned bh[2] = { Vsh[vb2 + qk], Vsh[vb2 + qk + 4] };
                unsigned bl[2] = { Vsl[vb2 + qk], Vsl[vb2 + qk + 4] };
                mma16816(o[nt2], ah, bh);
                mma16816(o[nt2], ah, bl);
                mma16816(o[nt2], al, bh);
            }
        }
        __syncthreads();
    }

    // ---- epilogue: normalize, fmask, split-store merged-head H ----
    const int grow0 = b*CN + qt*128 + wid*16 + qr;
    const int grow1 = grow0 + 8;
    float f0 = fmask[grow0] / l0;
    float f1 = fmask[grow1] / l1;
    #pragma unroll
    for (int nt2 = 0; nt2 < 8; nt2++) {
        int col = h*CHD + nt2*8 + qk*2;
        float v0 = o[nt2][0]*f0, v1 = o[nt2][1]*f0;
        float v2 = o[nt2][2]*f1, v3 = o[nt2][3]*f1;
        __nv_bfloat16 h0,lo0,h1,lo1,h2,lo2,h3,lo3;
        bsplit(v0,h0,lo0); bsplit(v1,h1,lo1);
        bsplit(v2,h2,lo2); bsplit(v3,h3,lo3);
        size_t i0 = (size_t)grow0*CO + col;
        size_t i1 = (size_t)grow1*CO + col;
        __nv_bfloat162 ph0; ph0.x=h0; ph0.y=h1;
        __nv_bfloat162 pl0; pl0.x=lo0; pl0.y=lo1;
        __nv_bfloat162 ph1; ph1.x=h2; ph1.y=h3;
        __nv_bfloat162 pl1; pl1.x=lo2; pl1.y=lo3;
        *(__nv_bfloat162*)(Hh + i0) = ph0;
        *(__nv_bfloat162*)(Hl + i0) = pl0;
        *(__nv_bfloat162*)(Hh + i1) = ph1;
        *(__nv_bfloat162*)(Hl + i1) = pl1;
    }
}

// ---------------------------------------------------------------------------
extern "C" void kernel_launch(void* const* d_in, const int* in_sizes, int n_in,
                              void* d_out, int out_size)
{
    const float* x = 0;  const unsigned char* mask_raw = 0;
    const float* slw = 0; const float* qkv_w = 0; const float* qkv_b = 0;
    const float* wbig[3] = {0,0,0}; const float* bsm[3] = {0,0,0};
    int nw = 0, nb = 0;

    for (int i = 0; i < n_in; i++) {
        switch (in_sizes[i]) {
            case 4194304: x        = (const float*)d_in[i]; break;
            case 8388608: /* adj unused */                  break;
            case 8192:    mask_raw = (const unsigned char*)d_in[i]; break;
            case 8:       slw      = (const float*)d_in[i]; break;
            case 786432:  qkv_w    = (const float*)d_in[i]; break;
            case 1536:    qkv_b    = (const float*)d_in[i]; break;
            case 262144:  if (nw < 3) wbig[nw++] = (const float*)d_in[i]; break;
            case 512:     if (nb < 3) bsm[nb++]  = (const float*)d_in[i]; break;
            default: break;
        }
    }
    const float *w1 = wbig[0], *w2 = wbig[1], *wr = wbig[2];
    const float *b1 = bsm[0],  *b2 = bsm[1],  *br = bsm[2];
    float* out = (float*)d_out;

    void *pf, *pxh, *pxl, *pqwh, *pqwl, *pw1h, *pw1l, *pw2h, *pw2l, *pwrh, *pwrl;
    void *pqh, *pql, *pHh, *pHl, *pTh, *pTl;
    cudaGetSymbolAddress(&pf,   g_fmask);
    cudaGetSymbolAddress(&pxh,  g_xh);   cudaGetSymbolAddress(&pxl,  g_xl);
    cudaGetSymbolAddress(&pqwh, g_qwh);  cudaGetSymbolAddress(&pqwl, g_qwl);
    cudaGetSymbolAddress(&pw1h, g_w1h);  cudaGetSymbolAddress(&pw1l, g_w1l);
    cudaGetSymbolAddress(&pw2h, g_w2h);  cudaGetSymbolAddress(&pw2l, g_w2l);
    cudaGetSymbolAddress(&pwrh, g_wrh);  cudaGetSymbolAddress(&pwrl, g_wrl);
    cudaGetSymbolAddress(&pqh,  g_qh);   cudaGetSymbolAddress(&pql,  g_ql);
    cudaGetSymbolAddress(&pHh,  g_Hh);   cudaGetSymbolAddress(&pHl,  g_Hl);
    cudaGetSymbolAddress(&pTh,  g_Th);   cudaGetSymbolAddress(&pTl,  g_Tl);

    float* fmp = (float*)pf;
    __nv_bfloat16 *xh=(__nv_bfloat16*)pxh, *xl=(__nv_bfloat16*)pxl;
    __nv_bfloat16 *qwh=(__nv_bfloat16*)pqwh, *qwl=(__nv_bfloat16*)pqwl;
    __nv_bfloat16 *w1h=(__nv_bfloat16*)pw1h, *w1l=(__nv_bfloat16*)pw1l;
    __nv_bfloat16 *w2h=(__nv_bfloat16*)pw2h, *w2l=(__nv_bfloat16*)pw2l;
    __nv_bfloat16 *wrh=(__nv_bfloat16*)pwrh, *wrl=(__nv_bfloat16*)pwrl;
    __nv_bfloat16 *qhp=(__nv_bfloat16*)pqh, *qlp=(__nv_bfloat16*)pql;
    __nv_bfloat16 *Hhp=(__nv_bfloat16*)pHh, *Hlp=(__nv_bfloat16*)pHl;
    __nv_bfloat16 *Thp=(__nv_bfloat16*)pTh, *Tlp=(__nv_bfloat16*)pTl;

    static int smem_set = 0;
    if (!smem_set) {
        cudaFuncSetAttribute(flash_tc, cudaFuncAttributeMaxDynamicSharedMemorySize,
                             FL_SMEM_BYTES);
        smem_set = 1;
    }

    // 0) mask convert + one-time splits
    mask_convert<<<1, 256>>>(mask_raw, fmp);
    split_kernel<<<(MROWS*CD+255)/256, 256>>>(x,     xh,  xl,  MROWS*CD);
    split_kernel<<<(QKVLD*CD+255)/256, 256>>>(qkv_w, qwh, qwl, QKVLD*CD);
    split_kernel<<<(CO*CO+255)/256,    256>>>(w1,    w1h, w1l, CO*CO);
    split_kernel<<<(CO*CO+255)/256,    256>>>(w2,    w2h, w2l, CO*CO);
    split_kernel<<<(CO*CD+255)/256,    256>>>(wr,    wrh, wrl, CO*CD);

    // 1) QKV = x @ qkv_w^T + qkv_b  -> split bf16
    gemm_tc<0><<<dim3(12, 64), 256>>>(xh, xl, qwh, qwl, qkv_b, fmp,
                                      (float*)0, qhp, qlp, CD, CD, CD, QKVLD);

    // 2-4) flash-fused attention -> split H (merged-head layout)
    flash_tc<<<dim3(CN/128, CB*CH), 256, FL_SMEM_BYTES>>>(qhp, qlp, slw, fmp, Hhp, Hlp);

    // 5) T = relu(H @ w1^T + b1) -> split bf16
    gemm_tc<1><<<dim3(4, 64), 256>>>(Hhp, Hlp, w1h, w1l, b1, fmp,
                                     (float*)0, Thp, Tlp, CO, CO, CO, CO);

    // 6) out = 0.5*(x @ wr^T + br)
    gemm_tc<2><<<dim3(4, 64), 256>>>(xh, xl, wrh, wrl, br, fmp,
                                     out, (__nv_bfloat16*)0, (__nv_bfloat16*)0, CD, CD, CD, CO);

    // 7) out += 0.5*fmask*(T @ w2^T + b2)
    gemm_tc<3><<<dim3(4, 64), 256>>>(Thp, Tlp, w2h, w2l, b2, fmp,
                                     out, (__nv_bfloat16*)0, (__nv_bfloat16*)0, CO, CO, CO, CO);
}